// round 7
// baseline (speedup 1.0000x reference)
#include <cuda_runtime.h>
#include <cuda_bf16.h>
#include <stdint.h>

#define NNODE 1000000
#define NEDGE 8000000

// Scratch in __device__ globals (zero-initialized at module load; each
// invocation leaves them ready-for-next-run — no allocation, no k_zero).
__device__ float  g_deg [NNODE];   // in-degree at dst (excl. self-loop); reset in k_prep
__device__ float  g_dinv[NNODE];   // rsqrt(deg + 1)
__device__ float4 g_xs  [NNODE];   // x * dinv
__device__ float4 g_acc1[NNODE];   // layer-1 accumulator; zeroed in k_prep
__device__ float2 g_gs  [NNODE];   // (relu(A1 x W1 + b1) W2) * dinv
__device__ float2 g_acc2[NNODE];   // layer-2 accumulator; zeroed in k_mid

// ---------------------------------------------------------------------------
// PDL intrinsics
__device__ __forceinline__ void pdl_wait() {
    asm volatile("griddepcontrol.wait;" ::: "memory");
}
__device__ __forceinline__ void pdl_trigger() {
    asm volatile("griddepcontrol.launch_dependents;" ::: "memory");
}

__device__ __forceinline__ void red_v4(float4* p, float4 v) {
    asm volatile("red.global.add.v4.f32 [%0], {%1,%2,%3,%4};"
                 :: "l"(p), "f"(v.x), "f"(v.y), "f"(v.z), "f"(v.w) : "memory");
}
__device__ __forceinline__ void red_v2(float2* p, float2 v) {
    asm volatile("red.global.add.v2.f32 [%0], {%1,%2};"
                 :: "l"(p), "f"(v.x), "f"(v.y) : "memory");
}
// streaming (evict-first) int4 load for edge-index streams
__device__ __forceinline__ int4 ldcs_i4(const int* p) {
    return __ldcs((const int4*)p);
}

// ---------------------------------------------------------------------------
// 1. in-degree at dst — 4 edges/thread, streaming idx loads
__global__ void __launch_bounds__(256) k_deg(const int* __restrict__ dst, int e) {
    int base = (blockIdx.x * blockDim.x + threadIdx.x) * 4;
    if (base + 4 <= e) {
        int4 d = ldcs_i4(dst + base);
        atomicAdd(&g_deg[d.x], 1.0f);
        atomicAdd(&g_deg[d.y], 1.0f);
        atomicAdd(&g_deg[d.z], 1.0f);
        atomicAdd(&g_deg[d.w], 1.0f);
    } else {
        for (int i = base; i < e; i++) atomicAdd(&g_deg[dst[i]], 1.0f);
    }
    pdl_trigger();
}

// ---------------------------------------------------------------------------
// 2. dinv + pre-scaled features; zeros acc1; self-cleans deg for next replay
__global__ void __launch_bounds__(256) k_prep(const float4* __restrict__ x, int n) {
    pdl_wait();
    int i = blockIdx.x * blockDim.x + threadIdx.x;
    if (i < n) {
        float di = rsqrtf(g_deg[i] + 1.0f);   // self-loop -> deg >= 1
        g_deg[i]  = 0.0f;                     // ready for next invocation
        g_dinv[i] = di;
        float4 v = __ldcs(&x[i]);             // streamed once, don't cache
        v.x *= di; v.y *= di; v.z *= di; v.w *= di;
        g_xs[i]   = v;
        g_acc1[i] = make_float4(0.f, 0.f, 0.f, 0.f);
    }
    pdl_trigger();
}

// ---------------------------------------------------------------------------
// 3. layer-1 scatter: acc1[dst] += xs[src] — 4 edges/thread
__global__ void __launch_bounds__(256) k_scatter1(const int* __restrict__ src,
                                                  const int* __restrict__ dst, int e) {
    pdl_wait();
    int base = (blockIdx.x * blockDim.x + threadIdx.x) * 4;
    if (base + 4 <= e) {
        int4 s = ldcs_i4(src + base);
        int4 d = ldcs_i4(dst + base);
        float4 v0 = g_xs[s.x];
        float4 v1 = g_xs[s.y];
        float4 v2 = g_xs[s.z];
        float4 v3 = g_xs[s.w];
        red_v4(&g_acc1[d.x], v0);
        red_v4(&g_acc1[d.y], v1);
        red_v4(&g_acc1[d.z], v2);
        red_v4(&g_acc1[d.w], v3);
    } else {
        for (int i = base; i < e; i++)
            red_v4(&g_acc1[dst[i]], g_xs[src[i]]);
    }
    pdl_trigger();
}

// ---------------------------------------------------------------------------
// 4. fused node transform; zeros acc2
__global__ void __launch_bounds__(256) k_mid(const float* __restrict__ W1,
                                             const float* __restrict__ b1,
                                             const float* __restrict__ W2,
                                             int n) {
    __shared__ float sW1[256];
    __shared__ float sb1[64];
    __shared__ float sW2[128];
    int t = threadIdx.x;
    if (t < 256) sW1[t] = W1[t];   // read-only inputs: safe before pdl_wait
    if (t < 64)  sb1[t] = b1[t];
    if (t < 128) sW2[t] = W2[t];
    pdl_wait();
    __syncthreads();

    int i = blockIdx.x * blockDim.x + t;
    if (i >= n) return;

    float di = g_dinv[i];
    float4 a  = g_acc1[i];
    float4 xs = g_xs[i];
    float a0 = di * (a.x + xs.x);
    float a1 = di * (a.y + xs.y);
    float a2 = di * (a.z + xs.z);
    float a3 = di * (a.w + xs.w);

    float o0 = 0.f, o1 = 0.f;
#pragma unroll
    for (int j = 0; j < 64; j++) {
        float h = sb1[j];
        h = fmaf(a0, sW1[j],       h);
        h = fmaf(a1, sW1[64 + j],  h);
        h = fmaf(a2, sW1[128 + j], h);
        h = fmaf(a3, sW1[192 + j], h);
        h = fmaxf(h, 0.f);
        o0 = fmaf(h, sW2[2 * j],     o0);
        o1 = fmaf(h, sW2[2 * j + 1], o1);
    }
    g_gs[i]   = make_float2(o0 * di, o1 * di);
    g_acc2[i] = make_float2(0.f, 0.f);
    pdl_trigger();
}

// ---------------------------------------------------------------------------
// 5. layer-2 scatter: acc2[dst] += gs[src] — 4 edges/thread
__global__ void __launch_bounds__(256) k_scatter2(const int* __restrict__ src,
                                                  const int* __restrict__ dst, int e) {
    pdl_wait();
    int base = (blockIdx.x * blockDim.x + threadIdx.x) * 4;
    if (base + 4 <= e) {
        int4 s = ldcs_i4(src + base);
        int4 d = ldcs_i4(dst + base);
        float2 v0 = g_gs[s.x];
        float2 v1 = g_gs[s.y];
        float2 v2 = g_gs[s.z];
        float2 v3 = g_gs[s.w];
        red_v2(&g_acc2[d.x], v0);
        red_v2(&g_acc2[d.y], v1);
        red_v2(&g_acc2[d.z], v2);
        red_v2(&g_acc2[d.w], v3);
    } else {
        for (int i = base; i < e; i++)
            red_v2(&g_acc2[dst[i]], g_gs[src[i]]);
    }
    pdl_trigger();
}

// ---------------------------------------------------------------------------
// 6. final: out = dinv * (acc2 + gs) + b2
__global__ void __launch_bounds__(256) k_final(const float* __restrict__ b2,
                                               float2* __restrict__ out, int n) {
    float bx = __ldg(&b2[0]);
    float by = __ldg(&b2[1]);
    pdl_wait();
    int i = blockIdx.x * blockDim.x + threadIdx.x;
    if (i < n) {
        float di = g_dinv[i];
        float2 a = g_acc2[i];
        float2 g = g_gs[i];
        out[i] = make_float2(di * (a.x + g.x) + bx,
                             di * (a.y + g.y) + by);
    }
}

// ---------------------------------------------------------------------------
// PDL launch helper
template <typename... Args>
static void pdl_launch(void (*kern)(Args...), int grid, int block,
                       Args... args) {
    cudaLaunchConfig_t cfg = {};
    cfg.gridDim  = dim3(grid, 1, 1);
    cfg.blockDim = dim3(block, 1, 1);
    cfg.dynamicSmemBytes = 0;
    cfg.stream = 0;
    cudaLaunchAttribute attr[1];
    attr[0].id = cudaLaunchAttributeProgrammaticStreamSerialization;
    attr[0].val.programmaticStreamSerializationAllowed = 1;
    cfg.attrs = attr;
    cfg.numAttrs = 1;
    cudaLaunchKernelEx(&cfg, kern, args...);
}

extern "C" void kernel_launch(void* const* d_in, const int* in_sizes, int n_in,
                              void* d_out, int out_size) {
    const float* x  = (const float*)d_in[0];   // [N,4]
    const int*   ei = (const int*)d_in[1];     // [2,E]  int32
    const float* W1 = (const float*)d_in[2];   // [4,64]
    const float* b1 = (const float*)d_in[3];   // [64]
    const float* W2 = (const float*)d_in[4];   // [64,2]
    const float* b2 = (const float*)d_in[5];   // [2]
    float2*      out = (float2*)d_out;         // [N,2]

    const int n = in_sizes[0] / 4;
    const int e = in_sizes[1] / 2;
    const int* src = ei;
    const int* dst = ei + e;

    const int T = 256;
    const int gn  = (n + T - 1) / T;
    const int ge4 = ((e + 3) / 4 + T - 1) / T;   // 4 edges/thread

    pdl_launch(k_deg,      ge4, T, dst, e);
    pdl_launch(k_prep,     gn,  T, (const float4*)x, n);
    pdl_launch(k_scatter1, ge4, T, src, dst, e);
    pdl_launch(k_mid,      gn,  T, W1, b1, W2, n);
    pdl_launch(k_scatter2, ge4, T, src, dst, e);
    pdl_launch(k_final,    gn,  T, b2, out, n);
}

// round 8
// speedup vs baseline: 1.0147x; 1.0147x over previous
#include <cuda_runtime.h>
#include <cuda_bf16.h>
#include <stdint.h>

#define NNODE 1000000
#define NEDGE 8000000

// Scratch in __device__ globals (zero-initialized at module load; every
// invocation leaves them zeroed again — self-cleaning, no k_zero pass).
__device__ float  g_deg [NNODE];   // in-degree at dst; reset in k_prep after use
__device__ float  g_dinv[NNODE];   // rsqrt(deg + 1)
__device__ float4 g_xs  [NNODE];   // x * dinv
__device__ float4 g_acc1[NNODE];   // layer-1 accumulator; zeroed in k_prep
__device__ float2 g_gs  [NNODE];   // (relu(A1 x W1 + b1) W2) * dinv
__device__ float2 g_acc2[NNODE];   // layer-2 accumulator; zeroed in k_mid

// ---------------------------------------------------------------------------
// PDL intrinsics
__device__ __forceinline__ void pdl_wait() {
    asm volatile("griddepcontrol.wait;" ::: "memory");
}
__device__ __forceinline__ void pdl_trigger() {
    asm volatile("griddepcontrol.launch_dependents;" ::: "memory");
}

__device__ __forceinline__ void red_v4(float4* p, float4 v) {
    asm volatile("red.global.add.v4.f32 [%0], {%1,%2,%3,%4};"
                 :: "l"(p), "f"(v.x), "f"(v.y), "f"(v.z), "f"(v.w) : "memory");
}
__device__ __forceinline__ void red_v2(float2* p, float2 v) {
    asm volatile("red.global.add.v2.f32 [%0], {%1,%2};"
                 :: "l"(p), "f"(v.x), "f"(v.y) : "memory");
}

// ---------------------------------------------------------------------------
// 1. in-degree at dst — 4 edges/thread (default cache policy: R6 config)
__global__ void __launch_bounds__(256) k_deg(const int* __restrict__ dst, int e) {
    int base = (blockIdx.x * blockDim.x + threadIdx.x) * 4;
    if (base + 4 <= e) {
        int4 d = *(const int4*)(dst + base);
        atomicAdd(&g_deg[d.x], 1.0f);
        atomicAdd(&g_deg[d.y], 1.0f);
        atomicAdd(&g_deg[d.z], 1.0f);
        atomicAdd(&g_deg[d.w], 1.0f);
    } else {
        for (int i = base; i < e; i++) atomicAdd(&g_deg[dst[i]], 1.0f);
    }
    pdl_trigger();
}

// ---------------------------------------------------------------------------
// 2. dinv + pre-scaled features; zeros acc1; self-cleans deg for next replay
__global__ void __launch_bounds__(256) k_prep(const float4* __restrict__ x, int n) {
    pdl_wait();
    int i = blockIdx.x * blockDim.x + threadIdx.x;
    if (i < n) {
        float di = rsqrtf(g_deg[i] + 1.0f);   // self-loop -> deg >= 1
        g_deg[i]  = 0.0f;                     // ready for next invocation
        g_dinv[i] = di;
        float4 v = x[i];
        v.x *= di; v.y *= di; v.z *= di; v.w *= di;
        g_xs[i]   = v;
        g_acc1[i] = make_float4(0.f, 0.f, 0.f, 0.f);
    }
    pdl_trigger();
}

// ---------------------------------------------------------------------------
// 3. layer-1 scatter: acc1[dst] += xs[src] — 4 edges/thread (R6 config)
__global__ void __launch_bounds__(256) k_scatter1(const int* __restrict__ src,
                                                  const int* __restrict__ dst, int e) {
    pdl_wait();
    int base = (blockIdx.x * blockDim.x + threadIdx.x) * 4;
    if (base + 4 <= e) {
        int4 s = *(const int4*)(src + base);
        int4 d = *(const int4*)(dst + base);
        float4 v0 = g_xs[s.x];
        float4 v1 = g_xs[s.y];
        float4 v2 = g_xs[s.z];
        float4 v3 = g_xs[s.w];
        red_v4(&g_acc1[d.x], v0);
        red_v4(&g_acc1[d.y], v1);
        red_v4(&g_acc1[d.z], v2);
        red_v4(&g_acc1[d.w], v3);
    } else {
        for (int i = base; i < e; i++)
            red_v4(&g_acc1[dst[i]], g_xs[src[i]]);
    }
    pdl_trigger();
}

// ---------------------------------------------------------------------------
// 4. fused node transform; zeros acc2
__global__ void __launch_bounds__(256, 8) k_mid(const float* __restrict__ W1,
                                                const float* __restrict__ b1,
                                                const float* __restrict__ W2,
                                                int n) {
    __shared__ float sW1[256];
    __shared__ float sb1[64];
    __shared__ float sW2[128];
    int t = threadIdx.x;
    if (t < 256) sW1[t] = W1[t];   // read-only inputs: safe before pdl_wait
    if (t < 64)  sb1[t] = b1[t];
    if (t < 128) sW2[t] = W2[t];
    pdl_wait();
    __syncthreads();

    int i = blockIdx.x * blockDim.x + t;
    if (i >= n) return;

    float di = g_dinv[i];
    float4 a  = g_acc1[i];
    float4 xs = g_xs[i];
    float a0 = di * (a.x + xs.x);
    float a1 = di * (a.y + xs.y);
    float a2 = di * (a.z + xs.z);
    float a3 = di * (a.w + xs.w);

    float o0 = 0.f, o1 = 0.f;
#pragma unroll
    for (int j = 0; j < 64; j++) {
        float h = sb1[j];
        h = fmaf(a0, sW1[j],       h);
        h = fmaf(a1, sW1[64 + j],  h);
        h = fmaf(a2, sW1[128 + j], h);
        h = fmaf(a3, sW1[192 + j], h);
        h = fmaxf(h, 0.f);
        o0 = fmaf(h, sW2[2 * j],     o0);
        o1 = fmaf(h, sW2[2 * j + 1], o1);
    }
    g_gs[i]   = make_float2(o0 * di, o1 * di);
    g_acc2[i] = make_float2(0.f, 0.f);
    pdl_trigger();
}

// ---------------------------------------------------------------------------
// 5. layer-2 scatter: acc2[dst] += gs[src] — 4 edges/thread
__global__ void __launch_bounds__(256) k_scatter2(const int* __restrict__ src,
                                                  const int* __restrict__ dst, int e) {
    pdl_wait();
    int base = (blockIdx.x * blockDim.x + threadIdx.x) * 4;
    if (base + 4 <= e) {
        int4 s = *(const int4*)(src + base);
        int4 d = *(const int4*)(dst + base);
        float2 v0 = g_gs[s.x];
        float2 v1 = g_gs[s.y];
        float2 v2 = g_gs[s.z];
        float2 v3 = g_gs[s.w];
        red_v2(&g_acc2[d.x], v0);
        red_v2(&g_acc2[d.y], v1);
        red_v2(&g_acc2[d.z], v2);
        red_v2(&g_acc2[d.w], v3);
    } else {
        for (int i = base; i < e; i++)
            red_v2(&g_acc2[dst[i]], g_gs[src[i]]);
    }
    pdl_trigger();
}

// ---------------------------------------------------------------------------
// 6. final: out = dinv * (acc2 + gs) + b2
__global__ void __launch_bounds__(256) k_final(const float* __restrict__ b2,
                                               float2* __restrict__ out, int n) {
    float bx = __ldg(&b2[0]);
    float by = __ldg(&b2[1]);
    pdl_wait();
    int i = blockIdx.x * blockDim.x + threadIdx.x;
    if (i < n) {
        float di = g_dinv[i];
        float2 a = g_acc2[i];
        float2 g = g_gs[i];
        out[i] = make_float2(di * (a.x + g.x) + bx,
                             di * (a.y + g.y) + by);
    }
}

// ---------------------------------------------------------------------------
// PDL launch helper
template <typename... Args>
static void pdl_launch(void (*kern)(Args...), int grid, int block,
                       Args... args) {
    cudaLaunchConfig_t cfg = {};
    cfg.gridDim  = dim3(grid, 1, 1);
    cfg.blockDim = dim3(block, 1, 1);
    cfg.dynamicSmemBytes = 0;
    cfg.stream = 0;
    cudaLaunchAttribute attr[1];
    attr[0].id = cudaLaunchAttributeProgrammaticStreamSerialization;
    attr[0].val.programmaticStreamSerializationAllowed = 1;
    cfg.attrs = attr;
    cfg.numAttrs = 1;
    cudaLaunchKernelEx(&cfg, kern, args...);
}

extern "C" void kernel_launch(void* const* d_in, const int* in_sizes, int n_in,
                              void* d_out, int out_size) {
    const float* x  = (const float*)d_in[0];   // [N,4]
    const int*   ei = (const int*)d_in[1];     // [2,E]  int32
    const float* W1 = (const float*)d_in[2];   // [4,64]
    const float* b1 = (const float*)d_in[3];   // [64]
    const float* W2 = (const float*)d_in[4];   // [64,2]
    const float* b2 = (const float*)d_in[5];   // [2]
    float2*      out = (float2*)d_out;         // [N,2]

    const int n = in_sizes[0] / 4;
    const int e = in_sizes[1] / 2;
    const int* src = ei;
    const int* dst = ei + e;

    const int T = 256;
    const int gn  = (n + T - 1) / T;
    const int ge4 = ((e + 3) / 4 + T - 1) / T;   // 4 edges/thread

    pdl_launch(k_deg,      ge4, T, dst, e);
    pdl_launch(k_prep,     gn,  T, (const float4*)x, n);
    pdl_launch(k_scatter1, ge4, T, src, dst, e);
    pdl_launch(k_mid,      gn,  T, W1, b1, W2, n);
    pdl_launch(k_scatter2, ge4, T, src, dst, e);
    pdl_launch(k_final,    gn,  T, b2, out, n);
}

// round 9
// speedup vs baseline: 1.0493x; 1.0342x over previous
#include <cuda_runtime.h>
#include <cuda_bf16.h>
#include <stdint.h>

#define NNODE 1000000
#define NEDGE 8000000

// Scratch in __device__ globals (no allocation allowed).
__device__ float  g_deg [NNODE];   // in-degree at dst (excl. self-loop)
__device__ float  g_dinv[NNODE];   // rsqrt(deg + 1)
__device__ float4 g_xs  [NNODE];   // x * dinv
__device__ float4 g_acc1[NNODE];   // layer-1 accumulator; zeroed in k_prep
__device__ float2 g_gs  [NNODE];   // (relu(A1 x W1 + b1) W2) * dinv
__device__ float2 g_acc2[NNODE];   // layer-2 accumulator; zeroed in k_mid

// ---------------------------------------------------------------------------
// PDL intrinsics
__device__ __forceinline__ void pdl_wait() {
    asm volatile("griddepcontrol.wait;" ::: "memory");
}
__device__ __forceinline__ void pdl_trigger() {
    asm volatile("griddepcontrol.launch_dependents;" ::: "memory");
}

__device__ __forceinline__ void red_v4(float4* p, float4 v) {
    asm volatile("red.global.add.v4.f32 [%0], {%1,%2,%3,%4};"
                 :: "l"(p), "f"(v.x), "f"(v.y), "f"(v.z), "f"(v.w) : "memory");
}
__device__ __forceinline__ void red_v2(float2* p, float2 v) {
    asm volatile("red.global.add.v2.f32 [%0], {%1,%2};"
                 :: "l"(p), "f"(v.x), "f"(v.y) : "memory");
}

// ---------------------------------------------------------------------------
// 1. zero degree (acc1/acc2 zeroed inside streaming kernels)  [R6 config]
__global__ void __launch_bounds__(256) k_zero(int n) {
    int i = blockIdx.x * blockDim.x + threadIdx.x;
    if (i < n) g_deg[i] = 0.0f;
    pdl_trigger();
}

// ---------------------------------------------------------------------------
// 2. in-degree at dst — 4 edges/thread  [R6 config]
__global__ void __launch_bounds__(256) k_deg(const int* __restrict__ dst, int e) {
    pdl_wait();
    int base = (blockIdx.x * blockDim.x + threadIdx.x) * 4;
    if (base + 4 <= e) {
        int4 d = *(const int4*)(dst + base);
        atomicAdd(&g_deg[d.x], 1.0f);
        atomicAdd(&g_deg[d.y], 1.0f);
        atomicAdd(&g_deg[d.z], 1.0f);
        atomicAdd(&g_deg[d.w], 1.0f);
    } else {
        for (int i = base; i < e; i++) atomicAdd(&g_deg[dst[i]], 1.0f);
    }
    pdl_trigger();
}

// ---------------------------------------------------------------------------
// 3. dinv + pre-scaled features; zeros acc1  [R6 config]
__global__ void __launch_bounds__(256) k_prep(const float4* __restrict__ x, int n) {
    pdl_wait();
    int i = blockIdx.x * blockDim.x + threadIdx.x;
    if (i < n) {
        float di = rsqrtf(g_deg[i] + 1.0f);   // self-loop -> deg >= 1
        g_dinv[i] = di;
        float4 v = x[i];
        v.x *= di; v.y *= di; v.z *= di; v.w *= di;
        g_xs[i]   = v;
        g_acc1[i] = make_float4(0.f, 0.f, 0.f, 0.f);
    }
    pdl_trigger();
}

// ---------------------------------------------------------------------------
// 4. layer-1 scatter: acc1[dst] += xs[src] — 4 edges/thread  [R6 config]
__global__ void __launch_bounds__(256) k_scatter1(const int* __restrict__ src,
                                                  const int* __restrict__ dst, int e) {
    pdl_wait();
    int base = (blockIdx.x * blockDim.x + threadIdx.x) * 4;
    if (base + 4 <= e) {
        int4 s = *(const int4*)(src + base);
        int4 d = *(const int4*)(dst + base);
        float4 v0 = g_xs[s.x];
        float4 v1 = g_xs[s.y];
        float4 v2 = g_xs[s.z];
        float4 v3 = g_xs[s.w];
        red_v4(&g_acc1[d.x], v0);
        red_v4(&g_acc1[d.y], v1);
        red_v4(&g_acc1[d.z], v2);
        red_v4(&g_acc1[d.w], v3);
    } else {
        for (int i = base; i < e; i++)
            red_v4(&g_acc1[dst[i]], g_xs[src[i]]);
    }
    pdl_trigger();
}

// ---------------------------------------------------------------------------
// 5. fused node transform; zeros acc2.
//    Weights packed per-j into two float4s: {W1[0..3][j]} and {b1[j], W2[j][0],
//    W2[j][1], 0} -> inner loop is 2x LDS.128 + 7 math ops (issue-bound fix).
__global__ void __launch_bounds__(256) k_mid(const float* __restrict__ W1,   // [4,64]
                                             const float* __restrict__ b1,   // [64]
                                             const float* __restrict__ W2,   // [64,2]
                                             int n) {
    __shared__ float4 sWa[64];   // sWa[j] = {W1[0][j], W1[1][j], W1[2][j], W1[3][j]}
    __shared__ float4 sWb[64];   // sWb[j] = {b1[j], W2[j][0], W2[j][1], 0}
    int t = threadIdx.x;
    if (t < 64) {
        sWa[t] = make_float4(W1[t], W1[64 + t], W1[128 + t], W1[192 + t]);
        sWb[t] = make_float4(b1[t], W2[2 * t], W2[2 * t + 1], 0.f);
    }
    pdl_wait();
    __syncthreads();

    int i = blockIdx.x * blockDim.x + t;
    if (i >= n) return;

    float di = g_dinv[i];
    float4 a  = g_acc1[i];
    float4 xs = g_xs[i];
    float a0 = di * (a.x + xs.x);
    float a1 = di * (a.y + xs.y);
    float a2 = di * (a.z + xs.z);
    float a3 = di * (a.w + xs.w);

    float o0 = 0.f, o1 = 0.f;
#pragma unroll
    for (int j = 0; j < 64; j++) {
        float4 wa = sWa[j];
        float4 wb = sWb[j];
        float h = wb.x;
        h = fmaf(a0, wa.x, h);
        h = fmaf(a1, wa.y, h);
        h = fmaf(a2, wa.z, h);
        h = fmaf(a3, wa.w, h);
        h = fmaxf(h, 0.f);
        o0 = fmaf(h, wb.y, o0);
        o1 = fmaf(h, wb.z, o1);
    }
    g_gs[i]   = make_float2(o0 * di, o1 * di);
    g_acc2[i] = make_float2(0.f, 0.f);
    pdl_trigger();
}

// ---------------------------------------------------------------------------
// 6. layer-2 scatter: acc2[dst] += gs[src] — 4 edges/thread  [R6 config]
__global__ void __launch_bounds__(256) k_scatter2(const int* __restrict__ src,
                                                  const int* __restrict__ dst, int e) {
    pdl_wait();
    int base = (blockIdx.x * blockDim.x + threadIdx.x) * 4;
    if (base + 4 <= e) {
        int4 s = *(const int4*)(src + base);
        int4 d = *(const int4*)(dst + base);
        float2 v0 = g_gs[s.x];
        float2 v1 = g_gs[s.y];
        float2 v2 = g_gs[s.z];
        float2 v3 = g_gs[s.w];
        red_v2(&g_acc2[d.x], v0);
        red_v2(&g_acc2[d.y], v1);
        red_v2(&g_acc2[d.z], v2);
        red_v2(&g_acc2[d.w], v3);
    } else {
        for (int i = base; i < e; i++)
            red_v2(&g_acc2[dst[i]], g_gs[src[i]]);
    }
    pdl_trigger();
}

// ---------------------------------------------------------------------------
// 7. final: out = dinv * (acc2 + gs) + b2  [R6 config]
__global__ void __launch_bounds__(256) k_final(const float* __restrict__ b2,
                                               float2* __restrict__ out, int n) {
    float bx = __ldg(&b2[0]);
    float by = __ldg(&b2[1]);
    pdl_wait();
    int i = blockIdx.x * blockDim.x + threadIdx.x;
    if (i < n) {
        float di = g_dinv[i];
        float2 a = g_acc2[i];
        float2 g = g_gs[i];
        out[i] = make_float2(di * (a.x + g.x) + bx,
                             di * (a.y + g.y) + by);
    }
}

// ---------------------------------------------------------------------------
// PDL launch helper
template <typename... Args>
static void pdl_launch(void (*kern)(Args...), int grid, int block,
                       Args... args) {
    cudaLaunchConfig_t cfg = {};
    cfg.gridDim  = dim3(grid, 1, 1);
    cfg.blockDim = dim3(block, 1, 1);
    cfg.dynamicSmemBytes = 0;
    cfg.stream = 0;
    cudaLaunchAttribute attr[1];
    attr[0].id = cudaLaunchAttributeProgrammaticStreamSerialization;
    attr[0].val.programmaticStreamSerializationAllowed = 1;
    cfg.attrs = attr;
    cfg.numAttrs = 1;
    cudaLaunchKernelEx(&cfg, kern, args...);
}

extern "C" void kernel_launch(void* const* d_in, const int* in_sizes, int n_in,
                              void* d_out, int out_size) {
    const float* x  = (const float*)d_in[0];   // [N,4]
    const int*   ei = (const int*)d_in[1];     // [2,E]  int32
    const float* W1 = (const float*)d_in[2];   // [4,64]
    const float* b1 = (const float*)d_in[3];   // [64]
    const float* W2 = (const float*)d_in[4];   // [64,2]
    const float* b2 = (const float*)d_in[5];   // [2]
    float2*      out = (float2*)d_out;         // [N,2]

    const int n = in_sizes[0] / 4;
    const int e = in_sizes[1] / 2;
    const int* src = ei;
    const int* dst = ei + e;

    const int T = 256;
    const int gn  = (n + T - 1) / T;
    const int ge4 = ((e + 3) / 4 + T - 1) / T;   // 4 edges/thread

    pdl_launch(k_zero,     gn,  T, n);
    pdl_launch(k_deg,      ge4, T, dst, e);
    pdl_launch(k_prep,     gn,  T, (const float4*)x, n);
    pdl_launch(k_scatter1, ge4, T, src, dst, e);
    pdl_launch(k_mid,      gn,  T, W1, b1, W2, n);
    pdl_launch(k_scatter2, ge4, T, src, dst, e);
    pdl_launch(k_final,    gn,  T, b2, out, n);
}

// round 10
// speedup vs baseline: 1.0495x; 1.0002x over previous
#include <cuda_runtime.h>
#include <cuda_bf16.h>
#include <stdint.h>

#define NNODE 1000000
#define NEDGE 8000000

// Scratch in __device__ globals (no allocation allowed).
__device__ float  g_deg [NNODE];   // in-degree at dst (excl. self-loop)
__device__ float  g_dinv[NNODE];   // rsqrt(deg + 1)
__device__ float4 g_xs  [NNODE];   // x * dinv
__device__ float4 g_acc1[NNODE];   // layer-1 accumulator; zeroed in k_prep
__device__ float2 g_gs  [NNODE];   // (relu(A1 x W1 + b1) W2) * dinv
__device__ float2 g_acc2[NNODE];   // layer-2 accumulator; zeroed in k_mid

// ---------------------------------------------------------------------------
// PDL intrinsics
__device__ __forceinline__ void pdl_wait() {
    asm volatile("griddepcontrol.wait;" ::: "memory");
}
__device__ __forceinline__ void pdl_trigger() {
    asm volatile("griddepcontrol.launch_dependents;" ::: "memory");
}

__device__ __forceinline__ void red_v4(float4* p, float4 v) {
    asm volatile("red.global.add.v4.f32 [%0], {%1,%2,%3,%4};"
                 :: "l"(p), "f"(v.x), "f"(v.y), "f"(v.z), "f"(v.w) : "memory");
}
__device__ __forceinline__ void red_v2(float2* p, float2 v) {
    asm volatile("red.global.add.v2.f32 [%0], {%1,%2};"
                 :: "l"(p), "f"(v.x), "f"(v.y) : "memory");
}
// L2-only gathers (skip L1 allocation — random access, ~0% L1 hit rate)
__device__ __forceinline__ float4 ldcg_f4(const float4* p) { return __ldcg(p); }
__device__ __forceinline__ float2 ldcg_f2(const float2* p) { return __ldcg(p); }

// ---------------------------------------------------------------------------
// 1. zero degree (acc1/acc2 zeroed inside streaming kernels)  [R6 config]
__global__ void __launch_bounds__(256) k_zero(int n) {
    int i = blockIdx.x * blockDim.x + threadIdx.x;
    if (i < n) g_deg[i] = 0.0f;
    pdl_trigger();
}

// ---------------------------------------------------------------------------
// 2. in-degree at dst — 4 edges/thread  [R6 config]
__global__ void __launch_bounds__(256) k_deg(const int* __restrict__ dst, int e) {
    pdl_wait();
    int base = (blockIdx.x * blockDim.x + threadIdx.x) * 4;
    if (base + 4 <= e) {
        int4 d = *(const int4*)(dst + base);
        atomicAdd(&g_deg[d.x], 1.0f);
        atomicAdd(&g_deg[d.y], 1.0f);
        atomicAdd(&g_deg[d.z], 1.0f);
        atomicAdd(&g_deg[d.w], 1.0f);
    } else {
        for (int i = base; i < e; i++) atomicAdd(&g_deg[dst[i]], 1.0f);
    }
    pdl_trigger();
}

// ---------------------------------------------------------------------------
// 3. dinv + pre-scaled features; zeros acc1  [R6 config]
__global__ void __launch_bounds__(256) k_prep(const float4* __restrict__ x, int n) {
    pdl_wait();
    int i = blockIdx.x * blockDim.x + threadIdx.x;
    if (i < n) {
        float di = rsqrtf(g_deg[i] + 1.0f);   // self-loop -> deg >= 1
        g_dinv[i] = di;
        float4 v = x[i];
        v.x *= di; v.y *= di; v.z *= di; v.w *= di;
        g_xs[i]   = v;
        g_acc1[i] = make_float4(0.f, 0.f, 0.f, 0.f);
    }
    pdl_trigger();
}

// ---------------------------------------------------------------------------
// 4. layer-1 scatter: acc1[dst] += xs[src] — 4 edges/thread, L2-only gathers
__global__ void __launch_bounds__(256) k_scatter1(const int* __restrict__ src,
                                                  const int* __restrict__ dst, int e) {
    pdl_wait();
    int base = (blockIdx.x * blockDim.x + threadIdx.x) * 4;
    if (base + 4 <= e) {
        int4 s = *(const int4*)(src + base);
        int4 d = *(const int4*)(dst + base);
        float4 v0 = ldcg_f4(&g_xs[s.x]);
        float4 v1 = ldcg_f4(&g_xs[s.y]);
        float4 v2 = ldcg_f4(&g_xs[s.z]);
        float4 v3 = ldcg_f4(&g_xs[s.w]);
        red_v4(&g_acc1[d.x], v0);
        red_v4(&g_acc1[d.y], v1);
        red_v4(&g_acc1[d.z], v2);
        red_v4(&g_acc1[d.w], v3);
    } else {
        for (int i = base; i < e; i++)
            red_v4(&g_acc1[dst[i]], ldcg_f4(&g_xs[src[i]]));
    }
    pdl_trigger();
}

// ---------------------------------------------------------------------------
// 5. fused node transform; zeros acc2; per-j packed weights  [R9 config]
__global__ void __launch_bounds__(256) k_mid(const float* __restrict__ W1,   // [4,64]
                                             const float* __restrict__ b1,   // [64]
                                             const float* __restrict__ W2,   // [64,2]
                                             int n) {
    __shared__ float4 sWa[64];   // {W1[0][j], W1[1][j], W1[2][j], W1[3][j]}
    __shared__ float4 sWb[64];   // {b1[j], W2[j][0], W2[j][1], 0}
    int t = threadIdx.x;
    if (t < 64) {
        sWa[t] = make_float4(W1[t], W1[64 + t], W1[128 + t], W1[192 + t]);
        sWb[t] = make_float4(b1[t], W2[2 * t], W2[2 * t + 1], 0.f);
    }
    pdl_wait();
    __syncthreads();

    int i = blockIdx.x * blockDim.x + t;
    if (i >= n) return;

    float di = g_dinv[i];
    float4 a  = g_acc1[i];
    float4 xs = g_xs[i];
    float a0 = di * (a.x + xs.x);
    float a1 = di * (a.y + xs.y);
    float a2 = di * (a.z + xs.z);
    float a3 = di * (a.w + xs.w);

    float o0 = 0.f, o1 = 0.f;
#pragma unroll
    for (int j = 0; j < 64; j++) {
        float4 wa = sWa[j];
        float4 wb = sWb[j];
        float h = wb.x;
        h = fmaf(a0, wa.x, h);
        h = fmaf(a1, wa.y, h);
        h = fmaf(a2, wa.z, h);
        h = fmaf(a3, wa.w, h);
        h = fmaxf(h, 0.f);
        o0 = fmaf(h, wb.y, o0);
        o1 = fmaf(h, wb.z, o1);
    }
    g_gs[i]   = make_float2(o0 * di, o1 * di);
    g_acc2[i] = make_float2(0.f, 0.f);
    pdl_trigger();
}

// ---------------------------------------------------------------------------
// 6. layer-2 scatter: acc2[dst] += gs[src] — 4 edges/thread, L2-only gathers
__global__ void __launch_bounds__(256) k_scatter2(const int* __restrict__ src,
                                                  const int* __restrict__ dst, int e) {
    pdl_wait();
    int base = (blockIdx.x * blockDim.x + threadIdx.x) * 4;
    if (base + 4 <= e) {
        int4 s = *(const int4*)(src + base);
        int4 d = *(const int4*)(dst + base);
        float2 v0 = ldcg_f2(&g_gs[s.x]);
        float2 v1 = ldcg_f2(&g_gs[s.y]);
        float2 v2 = ldcg_f2(&g_gs[s.z]);
        float2 v3 = ldcg_f2(&g_gs[s.w]);
        red_v2(&g_acc2[d.x], v0);
        red_v2(&g_acc2[d.y], v1);
        red_v2(&g_acc2[d.z], v2);
        red_v2(&g_acc2[d.w], v3);
    } else {
        for (int i = base; i < e; i++)
            red_v2(&g_acc2[dst[i]], ldcg_f2(&g_gs[src[i]]));
    }
    pdl_trigger();
}

// ---------------------------------------------------------------------------
// 7. final: out = dinv * (acc2 + gs) + b2  [R6 config]
__global__ void __launch_bounds__(256) k_final(const float* __restrict__ b2,
                                               float2* __restrict__ out, int n) {
    float bx = __ldg(&b2[0]);
    float by = __ldg(&b2[1]);
    pdl_wait();
    int i = blockIdx.x * blockDim.x + threadIdx.x;
    if (i < n) {
        float di = g_dinv[i];
        float2 a = g_acc2[i];
        float2 g = g_gs[i];
        out[i] = make_float2(di * (a.x + g.x) + bx,
                             di * (a.y + g.y) + by);
    }
}

// ---------------------------------------------------------------------------
// PDL launch helper
template <typename... Args>
static void pdl_launch(void (*kern)(Args...), int grid, int block,
                       Args... args) {
    cudaLaunchConfig_t cfg = {};
    cfg.gridDim  = dim3(grid, 1, 1);
    cfg.blockDim = dim3(block, 1, 1);
    cfg.dynamicSmemBytes = 0;
    cfg.stream = 0;
    cudaLaunchAttribute attr[1];
    attr[0].id = cudaLaunchAttributeProgrammaticStreamSerialization;
    attr[0].val.programmaticStreamSerializationAllowed = 1;
    cfg.attrs = attr;
    cfg.numAttrs = 1;
    cudaLaunchKernelEx(&cfg, kern, args...);
}

extern "C" void kernel_launch(void* const* d_in, const int* in_sizes, int n_in,
                              void* d_out, int out_size) {
    const float* x  = (const float*)d_in[0];   // [N,4]
    const int*   ei = (const int*)d_in[1];     // [2,E]  int32
    const float* W1 = (const float*)d_in[2];   // [4,64]
    const float* b1 = (const float*)d_in[3];   // [64]
    const float* W2 = (const float*)d_in[4];   // [64,2]
    const float* b2 = (const float*)d_in[5];   // [2]
    float2*      out = (float2*)d_out;         // [N,2]

    const int n = in_sizes[0] / 4;
    const int e = in_sizes[1] / 2;
    const int* src = ei;
    const int* dst = ei + e;

    const int T = 256;
    const int gn  = (n + T - 1) / T;
    const int ge4 = ((e + 3) / 4 + T - 1) / T;   // 4 edges/thread

    pdl_launch(k_zero,     gn,  T, n);
    pdl_launch(k_deg,      ge4, T, dst, e);
    pdl_launch(k_prep,     gn,  T, (const float4*)x, n);
    pdl_launch(k_scatter1, ge4, T, src, dst, e);
    pdl_launch(k_mid,      gn,  T, W1, b1, W2, n);
    pdl_launch(k_scatter2, ge4, T, src, dst, e);
    pdl_launch(k_final,    gn,  T, b2, out, n);
}

// round 11
// speedup vs baseline: 1.0910x; 1.0395x over previous
#include <cuda_runtime.h>
#include <cuda_bf16.h>
#include <stdint.h>

#define NNODE 1000000
#define NEDGE 8000000

// Scratch in __device__ globals (zero-initialized at module load; g_deg is
// re-zeroed by k_final each run -> self-cleaning, no k_zero pass).
__device__ float  g_deg [NNODE];   // in-degree at dst; zeroed in k_final
__device__ float  g_dinv[NNODE];   // rsqrt(deg + 1)
__device__ float4 g_xs  [NNODE];   // x * dinv
__device__ float4 g_acc1[NNODE];   // layer-1 accumulator; zeroed in k_prep
__device__ float2 g_gs  [NNODE];   // (relu(A1 x W1 + b1) W2) * dinv
__device__ float2 g_acc2[NNODE];   // layer-2 accumulator; zeroed in k_mid

// ---------------------------------------------------------------------------
// PDL intrinsics
__device__ __forceinline__ void pdl_wait() {
    asm volatile("griddepcontrol.wait;" ::: "memory");
}
__device__ __forceinline__ void pdl_trigger() {
    asm volatile("griddepcontrol.launch_dependents;" ::: "memory");
}

__device__ __forceinline__ void red_v4(float4* p, float4 v) {
    asm volatile("red.global.add.v4.f32 [%0], {%1,%2,%3,%4};"
                 :: "l"(p), "f"(v.x), "f"(v.y), "f"(v.z), "f"(v.w) : "memory");
}
__device__ __forceinline__ void red_v2(float2* p, float2 v) {
    asm volatile("red.global.add.v2.f32 [%0], {%1,%2};"
                 :: "l"(p), "f"(v.x), "f"(v.y) : "memory");
}
__device__ __forceinline__ float4 ldcg_f4(const float4* p) { return __ldcg(p); }
__device__ __forceinline__ float2 ldcg_f2(const float2* p) { return __ldcg(p); }

// packed f32x2 helpers (sm_103a FFMA2 path)
#define PACK2(out, lo, hi) \
    asm("mov.b64 %0, {%1, %2};" : "=l"(out) : "f"(lo), "f"(hi))
#define UNPACK2(lo, hi, in) \
    asm("mov.b64 {%0, %1}, %2;" : "=f"(lo), "=f"(hi) : "l"(in))
#define FMA2(d, a, b, c) \
    asm("fma.rn.f32x2 %0, %1, %2, %3;" : "=l"(d) : "l"(a), "l"(b), "l"(c))

// ---------------------------------------------------------------------------
// 1. in-degree at dst — 4 edges/thread
__global__ void __launch_bounds__(256) k_deg(const int* __restrict__ dst, int e) {
    pdl_wait();
    int base = (blockIdx.x * blockDim.x + threadIdx.x) * 4;
    if (base + 4 <= e) {
        int4 d = *(const int4*)(dst + base);
        atomicAdd(&g_deg[d.x], 1.0f);
        atomicAdd(&g_deg[d.y], 1.0f);
        atomicAdd(&g_deg[d.z], 1.0f);
        atomicAdd(&g_deg[d.w], 1.0f);
    } else {
        for (int i = base; i < e; i++) atomicAdd(&g_deg[dst[i]], 1.0f);
    }
    pdl_trigger();
}

// ---------------------------------------------------------------------------
// 2. dinv + pre-scaled features; zeros acc1
__global__ void __launch_bounds__(256) k_prep(const float4* __restrict__ x, int n) {
    pdl_wait();
    int i = blockIdx.x * blockDim.x + threadIdx.x;
    if (i < n) {
        float di = rsqrtf(g_deg[i] + 1.0f);   // self-loop -> deg >= 1
        g_dinv[i] = di;
        float4 v = x[i];
        v.x *= di; v.y *= di; v.z *= di; v.w *= di;
        g_xs[i]   = v;
        g_acc1[i] = make_float4(0.f, 0.f, 0.f, 0.f);
    }
    pdl_trigger();
}

// ---------------------------------------------------------------------------
// 3. layer-1 scatter: acc1[dst] += xs[src] — 4 edges/thread
__global__ void __launch_bounds__(256) k_scatter1(const int* __restrict__ src,
                                                  const int* __restrict__ dst, int e) {
    pdl_wait();
    int base = (blockIdx.x * blockDim.x + threadIdx.x) * 4;
    if (base + 4 <= e) {
        int4 s = *(const int4*)(src + base);
        int4 d = *(const int4*)(dst + base);
        float4 v0 = ldcg_f4(&g_xs[s.x]);
        float4 v1 = ldcg_f4(&g_xs[s.y]);
        float4 v2 = ldcg_f4(&g_xs[s.z]);
        float4 v3 = ldcg_f4(&g_xs[s.w]);
        red_v4(&g_acc1[d.x], v0);
        red_v4(&g_acc1[d.y], v1);
        red_v4(&g_acc1[d.z], v2);
        red_v4(&g_acc1[d.w], v3);
    } else {
        for (int i = base; i < e; i++)
            red_v4(&g_acc1[dst[i]], ldcg_f4(&g_xs[src[i]]));
    }
    pdl_trigger();
}

// ---------------------------------------------------------------------------
// 4. fused node transform; zeros acc2. Inner loop in packed f32x2 (FFMA2):
//    process j-pairs; h chain keeps the exact scalar fma order per element.
__global__ void __launch_bounds__(256) k_mid(const float* __restrict__ W1,   // [4,64]
                                             const float* __restrict__ b1,   // [64]
                                             const float* __restrict__ W2,   // [64,2]
                                             int n) {
    __shared__ float4 sA[32];   // {W1[0][j],W1[0][j+1], W1[1][j],W1[1][j+1]}
    __shared__ float4 sB[32];   // {W1[2][j],W1[2][j+1], W1[3][j],W1[3][j+1]}
    __shared__ float4 sC[32];   // {b1[j],b1[j+1], W2[j][0],W2[j+1][0]}
    __shared__ float2 sD[32];   // {W2[j][1], W2[j+1][1]}
    int t = threadIdx.x;
    if (t < 32) {
        int j = 2 * t;
        sA[t] = make_float4(W1[j],       W1[j + 1],       W1[64 + j],  W1[64 + j + 1]);
        sB[t] = make_float4(W1[128 + j], W1[128 + j + 1], W1[192 + j], W1[192 + j + 1]);
        sC[t] = make_float4(b1[j],       b1[j + 1],       W2[2 * j],   W2[2 * j + 2]);
        sD[t] = make_float2(W2[2 * j + 1], W2[2 * j + 3]);
    }
    pdl_wait();
    __syncthreads();

    int i = blockIdx.x * blockDim.x + t;
    if (i >= n) return;

    float di = g_dinv[i];
    float4 a  = g_acc1[i];
    float4 xs = g_xs[i];
    float a0 = di * (a.x + xs.x);
    float a1 = di * (a.y + xs.y);
    float a2 = di * (a.z + xs.z);
    float a3 = di * (a.w + xs.w);

    unsigned long long pa0, pa1, pa2, pa3, po0, po1;
    PACK2(pa0, a0, a0);
    PACK2(pa1, a1, a1);
    PACK2(pa2, a2, a2);
    PACK2(pa3, a3, a3);
    PACK2(po0, 0.f, 0.f);
    PACK2(po1, 0.f, 0.f);

#pragma unroll
    for (int j2 = 0; j2 < 32; j2++) {
        float4 A = sA[j2];
        float4 B = sB[j2];
        float4 C = sC[j2];
        float2 D = sD[j2];
        unsigned long long h2, w;
        PACK2(h2, C.x, C.y);                    // {b1[j], b1[j+1]}
        PACK2(w, A.x, A.y); FMA2(h2, pa0, w, h2);
        PACK2(w, A.z, A.w); FMA2(h2, pa1, w, h2);
        PACK2(w, B.x, B.y); FMA2(h2, pa2, w, h2);
        PACK2(w, B.z, B.w); FMA2(h2, pa3, w, h2);
        float hl, hh;
        UNPACK2(hl, hh, h2);                    // reg-pair alias, ~free
        hl = fmaxf(hl, 0.f);
        hh = fmaxf(hh, 0.f);
        PACK2(h2, hl, hh);
        PACK2(w, C.z, C.w); FMA2(po0, h2, w, po0);
        PACK2(w, D.x, D.y); FMA2(po1, h2, w, po1);
    }
    float p0l, p0h, p1l, p1h;
    UNPACK2(p0l, p0h, po0);
    UNPACK2(p1l, p1h, po1);
    float o0 = p0l + p0h;
    float o1 = p1l + p1h;

    g_gs[i]   = make_float2(o0 * di, o1 * di);
    g_acc2[i] = make_float2(0.f, 0.f);
    pdl_trigger();
}

// ---------------------------------------------------------------------------
// 5. layer-2 scatter: acc2[dst] += gs[src] — 4 edges/thread
__global__ void __launch_bounds__(256) k_scatter2(const int* __restrict__ src,
                                                  const int* __restrict__ dst, int e) {
    pdl_wait();
    int base = (blockIdx.x * blockDim.x + threadIdx.x) * 4;
    if (base + 4 <= e) {
        int4 s = *(const int4*)(src + base);
        int4 d = *(const int4*)(dst + base);
        float2 v0 = ldcg_f2(&g_gs[s.x]);
        float2 v1 = ldcg_f2(&g_gs[s.y]);
        float2 v2 = ldcg_f2(&g_gs[s.z]);
        float2 v3 = ldcg_f2(&g_gs[s.w]);
        red_v2(&g_acc2[d.x], v0);
        red_v2(&g_acc2[d.y], v1);
        red_v2(&g_acc2[d.z], v2);
        red_v2(&g_acc2[d.w], v3);
    } else {
        for (int i = base; i < e; i++)
            red_v2(&g_acc2[dst[i]], ldcg_f2(&g_gs[src[i]]));
    }
    pdl_trigger();
}

// ---------------------------------------------------------------------------
// 6. final: out = dinv * (acc2 + gs) + b2; re-zeroes deg for the next run
__global__ void __launch_bounds__(256) k_final(const float* __restrict__ b2,
                                               float2* __restrict__ out, int n) {
    float bx = __ldg(&b2[0]);
    float by = __ldg(&b2[1]);
    pdl_wait();
    int i = blockIdx.x * blockDim.x + threadIdx.x;
    if (i < n) {
        float di = g_dinv[i];
        float2 a = g_acc2[i];
        float2 g = g_gs[i];
        out[i] = make_float2(di * (a.x + g.x) + bx,
                             di * (a.y + g.y) + by);
        g_deg[i] = 0.0f;   // self-clean: ready for next invocation/replay
    }
}

// ---------------------------------------------------------------------------
// PDL launch helper
template <typename... Args>
static void pdl_launch(void (*kern)(Args...), int grid, int block,
                       Args... args) {
    cudaLaunchConfig_t cfg = {};
    cfg.gridDim  = dim3(grid, 1, 1);
    cfg.blockDim = dim3(block, 1, 1);
    cfg.dynamicSmemBytes = 0;
    cfg.stream = 0;
    cudaLaunchAttribute attr[1];
    attr[0].id = cudaLaunchAttributeProgrammaticStreamSerialization;
    attr[0].val.programmaticStreamSerializationAllowed = 1;
    cfg.attrs = attr;
    cfg.numAttrs = 1;
    cudaLaunchKernelEx(&cfg, kern, args...);
}

extern "C" void kernel_launch(void* const* d_in, const int* in_sizes, int n_in,
                              void* d_out, int out_size) {
    const float* x  = (const float*)d_in[0];   // [N,4]
    const int*   ei = (const int*)d_in[1];     // [2,E]  int32
    const float* W1 = (const float*)d_in[2];   // [4,64]
    const float* b1 = (const float*)d_in[3];   // [64]
    const float* W2 = (const float*)d_in[4];   // [64,2]
    const float* b2 = (const float*)d_in[5];   // [2]
    float2*      out = (float2*)d_out;         // [N,2]

    const int n = in_sizes[0] / 4;
    const int e = in_sizes[1] / 2;
    const int* src = ei;
    const int* dst = ei + e;

    const int T = 256;
    const int gn  = (n + T - 1) / T;
    const int ge4 = ((e + 3) / 4 + T - 1) / T;   // 4 edges/thread

    pdl_launch(k_deg,      ge4, T, dst, e);
    pdl_launch(k_prep,     gn,  T, (const float4*)x, n);
    pdl_launch(k_scatter1, ge4, T, src, dst, e);
    pdl_launch(k_mid,      gn,  T, W1, b1, W2, n);
    pdl_launch(k_scatter2, ge4, T, src, dst, e);
    pdl_launch(k_final,    gn,  T, b2, out, n);
}